// round 10
// baseline (speedup 1.0000x reference)
#include <cuda_runtime.h>
#include <cuda_fp16.h>

#define G       8
#define CC      128
#define LL      3
#define HH      256
#define EPS_FA  0.1f
#define EMAX    1048576
#define SBINS   512

// ---------------- scratch (device globals; no allocations) ----------------
__device__ __half  g_xh [131072 * CC];         // half copy of original x
__device__ __half  g_h0 [131072 * CC];         // layer-0 h (half), orig-id indexed
__device__ __half  g_h1 [131072 * CC];         // layer-1 h (half), orig-id indexed
__device__ int     g_csr0[EMAX];
__device__ __align__(16) int g_deg0[131072];
__device__ int     g_scoreA[131072], g_scoreB[65536];
__device__ __align__(16) int g_offs0[131072];
__device__ unsigned g_state0[64];
__device__ int     g_nmapA[131072], g_nmapB[65536];
__device__ int     g_permA[65536], g_permB[32768];
__device__ float2  g_pack0[131072];            // {ar0, dinv0}
__device__ float2  g_pack1[131072];            // {ar1, dinv1 or 0 if dropped}
__device__ float2  g_pack2[131072];            // {ar2, dinv2 or 0 if dropped}
__device__ float   g_al0[131072], g_al1[131072], g_al2[131072];
__device__ float   g_pool[LL * G * CC];

__device__ __forceinline__ float2 h2f(unsigned u)
{
    __half2 h = *reinterpret_cast<__half2*>(&u);
    return __half22float2(h);
}

// ---------------- kernels ----------------

__global__ void k_zero()
{
    int i = blockIdx.x * blockDim.x + threadIdx.x;   // 131072 threads
    g_deg0[i] = 0; g_scoreA[i] = 0;
    g_pack1[i] = make_float2(0.f, 0.f);
    g_pack2[i] = make_float2(0.f, 0.f);
    if (i < 65536) g_scoreB[i] = 0;
    if (i < LL * G * CC) g_pool[i] = 0.0f;
    if (i < 64) g_state0[i] = 0u;
}

__global__ void k_degree(const int* __restrict__ src, const int* __restrict__ dst, int E)
{
    int i = blockIdx.x * blockDim.x + threadIdx.x;   // E/4 threads via int4
    int n4 = E >> 2;
    for (int e = i; e < n4; e += gridDim.x * blockDim.x) {
        int4 d = ((const int4*)dst)[e];
        int4 s = ((const int4*)src)[e];
        atomicAdd(&g_deg0[d.x], 1); atomicAdd(&g_deg0[d.y], 1);
        atomicAdd(&g_deg0[d.z], 1); atomicAdd(&g_deg0[d.w], 1);
        atomicAdd(&g_scoreA[s.x], 1); atomicAdd(&g_scoreA[s.y], 1);
        atomicAdd(&g_scoreA[s.z], 1); atomicAdd(&g_scoreA[s.w], 1);
    }
    // E is a multiple of 4 here (G*N0*DEG), no tail needed
}

// exclusive scan of deg0 (decoupled lookback) + write pack0.y = rsqrt(deg+1)
__global__ void __launch_bounds__(1024, 1) k_scan()
{
    __shared__ int sh[1024];
    __shared__ int s_base;
    int tid = threadIdx.x, b = blockIdx.x;
    int gi = b * 4096 + tid * 4;
    int4 v = *(const int4*)(g_deg0 + gi);
    g_pack0[gi + 0].y = rsqrtf((float)v.x + 1.0f);
    g_pack0[gi + 1].y = rsqrtf((float)v.y + 1.0f);
    g_pack0[gi + 2].y = rsqrtf((float)v.z + 1.0f);
    g_pack0[gi + 3].y = rsqrtf((float)v.w + 1.0f);
    int tsum = v.x + v.y + v.z + v.w;
    sh[tid] = tsum;
    __syncthreads();
    int acc = tsum;
#pragma unroll
    for (int off = 1; off < 1024; off <<= 1) {
        int add = (tid >= off) ? sh[tid - off] : 0;
        __syncthreads();
        acc += add;
        sh[tid] = acc;
        __syncthreads();
    }
    int total = sh[1023];
    if (tid == 0 && b > 0)
        atomicExch(&g_state0[b], 0x40000000u | (unsigned)total);
    if (tid < 32) {
        int base = 0;
        if (b > 0) {
            int idx = b - 1 - tid;
            while (true) {
                unsigned s = 0;
                if (idx >= 0) { do { s = atomicAdd(&g_state0[idx], 0u); } while (s == 0u); }
                unsigned pm = __ballot_sync(0xffffffffu, idx >= 0 && (s & 0x80000000u));
                int firstP = pm ? (__ffs(pm) - 1) : 32;
                int c = (idx >= 0 && tid <= firstP) ? (int)(s & 0x3FFFFFFFu) : 0;
#pragma unroll
                for (int o = 16; o; o >>= 1) c += __shfl_xor_sync(0xffffffffu, c, o);
                base += c;
                if (pm) break;
                idx -= 32;
            }
        }
        if (tid == 0) {
            atomicExch(&g_state0[b], 0x80000000u | (unsigned)(base + total));
            s_base = base;
        }
    }
    __syncthreads();
    int excl = s_base + acc - tsum;
    int4 o;
    o.x = excl; o.y = excl + v.x; o.z = o.y + v.y; o.w = o.z + v.z;
    *(int4*)(g_offs0 + gi) = o;
}

// scatter edges into CSR-by-dst using offs0 itself as the cursor.
// After this kernel offs0[d] == start(d) + deg(d); consumers recompute start.
__global__ void k_scatter(const int* __restrict__ src, const int* __restrict__ dst, int E)
{
    for (int e = blockIdx.x * blockDim.x + threadIdx.x; e < E;
         e += gridDim.x * blockDim.x) {
        int p = atomicAdd(&g_offs0[dst[e]], 1);
        g_csr0[p] = src[e];
    }
}

// layer-0 node prep: pack0.x = ar0, al0, half copy of x
__global__ void k_nodeprep(const float* __restrict__ x,
                           const float* __restrict__ attl, const float* __restrict__ attr)
{
    int warp = (blockIdx.x * blockDim.x + threadIdx.x) >> 5;
    int lane = threadIdx.x & 31;
    float4 cv = __ldg((const float4*)(x + (size_t)warp * CC) + lane);
    float4 lv = ((const float4*)attl)[lane];
    float4 rv = ((const float4*)attr)[lane];
    float al = cv.x*lv.x + cv.y*lv.y + cv.z*lv.z + cv.w*lv.w;
    float ar = cv.x*rv.x + cv.y*rv.y + cv.z*rv.z + cv.w*rv.w;
#pragma unroll
    for (int o = 16; o; o >>= 1) {
        al += __shfl_xor_sync(0xffffffffu, al, o);
        ar += __shfl_xor_sync(0xffffffffu, ar, o);
    }
    if (lane == 0) { g_al0[warp] = al; g_pack0[warp].x = ar; }
    uint2 h;
    *reinterpret_cast<__half2*>(&h.x) = __floats2half2_rn(cv.x, cv.y);
    *reinterpret_cast<__half2*>(&h.y) = __floats2half2_rn(cv.z, cv.w);
    ((uint2*)(g_xh + (size_t)warp * CC))[lane] = h;
}

// unified aggregation: warp per dst node; masked walk of csr0; coef via pack
// (pack.y==0 encodes dropped source). All ids are orig ids.
// Gather processes TWO source rows per step: half-warps (16 lanes x 16B) each
// handle a different row; partial channel sums combined via shfl_xor(16).
template<int MODE>
__global__ void __launch_bounds__(256) k_agg(
                      const __half* __restrict__ feat,
                      const float2* __restrict__ pack,
                      const float* __restrict__ alC,
                      float* __restrict__ alN, float2* __restrict__ packN,
                      const float* __restrict__ attlN, const float* __restrict__ attrN,
                      __half* __restrict__ hout, int log2npg, int layer)
{
    __shared__ unsigned smax[128];
    __shared__ int2 spair[8][32];
    int tid  = threadIdx.x;
    int lane = tid & 31;
    int w    = tid >> 5;
    int half = lane >> 4;          // 0 or 1: which row of the pair
    int li   = lane & 15;          // 16B slot within a 256B row
    if (tid < 128) smax[tid] = 0;
    __syncthreads();

    int d = (blockIdx.x * blockDim.x + tid) >> 5;
    int old0;
    if (MODE == 0)      old0 = d;
    else if (MODE == 1) old0 = g_permA[d];
    else                old0 = g_permA[g_permB[d]];

    int cnt   = g_deg0[old0];
    int start = g_offs0[old0] - cnt;       // offs0 was advanced by scatter
    float2 pkS = __ldg(&pack[old0]);
    float dind = pkS.y;
    float ald  = alC[old0];

    float acc[8];
#pragma unroll
    for (int k = 0; k < 8; k++) acc[k] = 0.f;

    for (int base = 0; base < cnt; base += 32) {
        int j = base + lane;
        int s0 = 0; float2 sp = make_float2(0.f, 0.f);
        if (j < cnt) {
            s0 = g_csr0[start + j];
            sp = __ldg(&pack[s0]);
        }
        bool valid = (j < cnt) && (sp.y != 0.0f);
        float coef = 0.f;
        if (valid) coef = sp.y * dind * tanhf(ald + sp.x);
        unsigned bal = __ballot_sync(0xffffffffu, valid);
        int m = __popc(bal);
        if (valid) {
            int pos = __popc(bal & ((1u << lane) - 1u));
            spair[w][pos] = make_int2(s0, __float_as_int(coef));
        }
        __syncwarp();
        int t = 0;
        for (; t + 8 <= m; t += 8) {           // 8 rows = 4 pair-steps in flight
            uint4 p[4]; float c[4];
#pragma unroll
            for (int q = 0; q < 4; q++) {
                int2 pr = spair[w][t + 2*q + half];
                c[q] = __int_as_float(pr.y);
                p[q] = __ldg((const uint4*)(feat + (size_t)pr.x * CC) + li);
            }
#pragma unroll
            for (int q = 0; q < 4; q++) {
                float2 f0 = h2f(p[q].x), f1 = h2f(p[q].y);
                float2 f2 = h2f(p[q].z), f3 = h2f(p[q].w);
                acc[0] += c[q]*f0.x; acc[1] += c[q]*f0.y;
                acc[2] += c[q]*f1.x; acc[3] += c[q]*f1.y;
                acc[4] += c[q]*f2.x; acc[5] += c[q]*f2.y;
                acc[6] += c[q]*f3.x; acc[7] += c[q]*f3.y;
            }
        }
        for (; t + 2 <= m; t += 2) {           // one pair
            int2 pr = spair[w][t + half];
            float c = __int_as_float(pr.y);
            uint4 p = __ldg((const uint4*)(feat + (size_t)pr.x * CC) + li);
            float2 f0 = h2f(p.x), f1 = h2f(p.y), f2 = h2f(p.z), f3 = h2f(p.w);
            acc[0] += c*f0.x; acc[1] += c*f0.y;
            acc[2] += c*f1.x; acc[3] += c*f1.y;
            acc[4] += c*f2.x; acc[5] += c*f2.y;
            acc[6] += c*f3.x; acc[7] += c*f3.y;
        }
        if (t < m) {                            // odd tail: half 1 contributes 0
            int2 pr = spair[w][t];
            float c = half ? 0.f : __int_as_float(pr.y);
            uint4 p = __ldg((const uint4*)(feat + (size_t)pr.x * CC) + li);
            float2 f0 = h2f(p.x), f1 = h2f(p.y), f2 = h2f(p.z), f3 = h2f(p.w);
            acc[0] += c*f0.x; acc[1] += c*f0.y;
            acc[2] += c*f1.x; acc[3] += c*f1.y;
            acc[4] += c*f2.x; acc[5] += c*f2.y;
            acc[6] += c*f3.x; acc[7] += c*f3.y;
        }
        __syncwarp();
    }

    // combine the two half-warp partial sums (both halves end with full sums)
#pragma unroll
    for (int k = 0; k < 8; k++)
        acc[k] += __shfl_xor_sync(0xffffffffu, acc[k], 16);

    // self-loop + EPS*orig + relu, 8 channels per lane (channels 8*li..8*li+7)
    uint4 pc = __ldg((const uint4*)(feat + (size_t)old0 * CC) + li);
    uint4 po = (MODE == 0) ? pc
             : __ldg((const uint4*)(g_xh + (size_t)old0 * CC) + li);
    float c0 = dind * dind * tanhf(ald + pkS.x);
    float av[8];
    {
        float2 a0 = h2f(pc.x), a1 = h2f(pc.y), a2 = h2f(pc.z), a3 = h2f(pc.w);
        float2 b0 = h2f(po.x), b1 = h2f(po.y), b2 = h2f(po.z), b3 = h2f(po.w);
        av[0] = fmaxf(c0*a0.x + EPS_FA*b0.x + acc[0], 0.f);
        av[1] = fmaxf(c0*a0.y + EPS_FA*b0.y + acc[1], 0.f);
        av[2] = fmaxf(c0*a1.x + EPS_FA*b1.x + acc[2], 0.f);
        av[3] = fmaxf(c0*a1.y + EPS_FA*b1.y + acc[3], 0.f);
        av[4] = fmaxf(c0*a2.x + EPS_FA*b2.x + acc[4], 0.f);
        av[5] = fmaxf(c0*a2.y + EPS_FA*b2.y + acc[5], 0.f);
        av[6] = fmaxf(c0*a3.x + EPS_FA*b3.x + acc[6], 0.f);
        av[7] = fmaxf(c0*a3.y + EPS_FA*b3.y + acc[7], 0.f);
    }

    if (MODE < 2) {
        if (half == 0) {
            uint4 hh;
            *reinterpret_cast<__half2*>(&hh.x) = __floats2half2_rn(av[0], av[1]);
            *reinterpret_cast<__half2*>(&hh.y) = __floats2half2_rn(av[2], av[3]);
            *reinterpret_cast<__half2*>(&hh.z) = __floats2half2_rn(av[4], av[5]);
            *reinterpret_cast<__half2*>(&hh.w) = __floats2half2_rn(av[6], av[7]);
            ((uint4*)(hout + (size_t)old0 * CC))[li] = hh;
        }
        float4 l0 = ((const float4*)attlN)[2*li],     l1 = ((const float4*)attlN)[2*li + 1];
        float4 r0 = ((const float4*)attrN)[2*li],     r1 = ((const float4*)attrN)[2*li + 1];
        float aln = av[0]*l0.x + av[1]*l0.y + av[2]*l0.z + av[3]*l0.w
                  + av[4]*l1.x + av[5]*l1.y + av[6]*l1.z + av[7]*l1.w;
        float arn = av[0]*r0.x + av[1]*r0.y + av[2]*r0.z + av[3]*r0.w
                  + av[4]*r1.x + av[5]*r1.y + av[6]*r1.z + av[7]*r1.w;
        if (half) { aln = 0.f; arn = 0.f; }    // avoid double counting
#pragma unroll
        for (int o = 16; o; o >>= 1) {
            aln += __shfl_xor_sync(0xffffffffu, aln, o);
            arn += __shfl_xor_sync(0xffffffffu, arn, o);
        }
        if (lane == 0) { alN[old0] = aln; packN[old0].x = arn; }
    }

    if (half == 0) {
#pragma unroll
        for (int k = 0; k < 8; k++)
            atomicMax(&smax[8*li + k], __float_as_uint(av[k]));
    }
    __syncthreads();
    if (tid < 128) {
        int g = (int)((blockIdx.x * (blockDim.x >> 5)) >> log2npg);
        atomicMax((unsigned*)&g_pool[(layer * G + g) * CC + tid], smax[tid]);
    }
}

// fused exact stable top-k (counting rank), one block per graph, 1024 threads.
template<int ROUNDS>
__global__ void __launch_bounds__(1024, 1) k_rank(
                       const int* __restrict__ score, int* __restrict__ perm,
                       int* __restrict__ nmap, int kk)
{
    extern __shared__ int smem[];
    int* whist = smem;              // 32*512
    int* s_tot = smem + 32*512;     // 512
    int* s_cnt = s_tot + 512;       // 512
    int tid = threadIdx.x, w = tid >> 5, lane = tid & 31;
    int npg = ROUNDS * 1024;
    int nbase = blockIdx.x * npg + w * (ROUNDS * 32);

    for (int i = lane; i < 512; i += 32) whist[w*512 + i] = 0;
    __syncwarp();

    int seq[ROUNDS];
#pragma unroll
    for (int r = 0; r < ROUNDS; r++) {
        int i = nbase + r * 32 + lane;
        int s = min(score[i], SBINS - 1);
        unsigned mk = __match_any_sync(0xffffffffu, s);
        int intra = __popc(mk & ((1u << lane) - 1u));
        int cur = whist[w*512 + s];
        __syncwarp();
        if (intra == 0) whist[w*512 + s] = cur + __popc(mk);
        __syncwarp();
        seq[r] = cur + intra;
    }
    __syncthreads();

    if (tid < 512) {
        int run = 0;
        for (int ww = 0; ww < 32; ww++) {
            int v = whist[ww*512 + tid];
            whist[ww*512 + tid] = run;
            run += v;
        }
        s_tot[tid] = run;
        s_cnt[tid] = run;
    }
    __syncthreads();
    for (int off = 1; off < 512; off <<= 1) {
        int add = 0;
        if (tid < 512 && tid + off < 512) add = s_cnt[tid + off];
        __syncthreads();
        if (tid < 512) s_cnt[tid] += add;
        __syncthreads();
    }

#pragma unroll
    for (int r = 0; r < ROUNDS; r++) {
        int i = nbase + r * 32 + lane;
        int s = min(score[i], SBINS - 1);
        int rank = (s_cnt[s] - s_tot[s]) + whist[w*512 + s] + seq[r];
        int nm = -1;
        if (rank < kk) {
            int neu = blockIdx.x * kk + rank;
            perm[neu] = i;
            nm = neu;
        }
        nmap[i] = nm;
    }
}

// layer-1 masked degree + out-degree score + pack1.y
__global__ void k_degscore1()
{
    int j = blockIdx.x * blockDim.x + threadIdx.x;   // 0..65535
    int old0 = g_permA[j];
    int c = g_deg0[old0];
    int st = g_offs0[old0] - c;
    int dcur = 0;
    for (int k = 0; k < c; k++) {
        int s0 = g_csr0[st + k];
        int s1 = g_nmapA[s0];
        if (s1 >= 0) { dcur++; atomicAdd(&g_scoreB[s1], 1); }
    }
    g_pack1[old0].y = rsqrtf((float)dcur + 1.0f);
}

// layer-2 masked degree + pack2.y
__global__ void k_degscore2()
{
    int m = blockIdx.x * blockDim.x + threadIdx.x;   // 0..32767
    int old1 = g_permB[m];
    int old0 = g_permA[old1];
    int c = g_deg0[old0];
    int st = g_offs0[old0] - c;
    int dcur = 0;
    for (int k = 0; k < c; k++) {
        int s0 = g_csr0[st + k];
        int s1 = g_nmapA[s0];
        if (s1 >= 0 && g_nmapB[s1] >= 0) dcur++;
    }
    g_pack2[old0].y = rsqrtf((float)dcur + 1.0f);
}

// GRU (h0=0) + final linears + root residual
__global__ void k_head(const float* __restrict__ w_ih, const float* __restrict__ b_ih,
                       const float* __restrict__ b_hh,
                       const float* __restrict__ w_fin, const float* __restrict__ b_fin,
                       const float* __restrict__ w_root, const float* __restrict__ b_root,
                       const float* __restrict__ root, const float* __restrict__ alpha_p,
                       float* __restrict__ out)
{
    __shared__ float fused[LL * CC];
    __shared__ float hgru[HH];
    __shared__ float rootv[CC];
    int g = blockIdx.x, t = threadIdx.x;
    for (int i = t; i < LL * CC; i += 256) {
        int layer = i >> 7, c = i & 127;
        fused[i] = g_pool[layer * G * CC + g * CC + c];
    }
    if (t < CC) rootv[t] = root[g * CC + t];
    __syncthreads();

    float gr = b_ih[t], gz = b_ih[HH + t], gn = b_ih[2 * HH + t];
    const float* wr = w_ih + (size_t)t            * (LL * CC);
    const float* wz = w_ih + (size_t)(HH + t)     * (LL * CC);
    const float* wn = w_ih + (size_t)(2 * HH + t) * (LL * CC);
    for (int j = 0; j < LL * CC; j++) {
        float f = fused[j];
        gr += wr[j] * f; gz += wz[j] * f; gn += wn[j] * f;
    }
    float r  = 1.0f / (1.0f + expf(-(gr + b_hh[t])));
    float z  = 1.0f / (1.0f + expf(-(gz + b_hh[HH + t])));
    float nc = tanhf(gn + r * b_hh[2 * HH + t]);
    hgru[t] = (1.0f - z) * nc;
    __syncthreads();

    if (t < CC) {
        float acc = b_fin[t];
        const float* wf = w_fin + (size_t)t * HH;
        for (int j = 0; j < HH; j++) acc += wf[j] * hgru[j];
        float re = b_root[t];
        const float* wo = w_root + (size_t)t * CC;
        for (int j = 0; j < CC; j++) re += wo[j] * rootv[j];
        float a = *alpha_p;
        out[g * CC + t] = a * acc + (1.0f - a) * re;
    }
}

// ---------------- launch ----------------

extern "C" void kernel_launch(void* const* d_in, const int* in_sizes, int n_in,
                              void* d_out, int out_size)
{
    const float* x      = (const float*)d_in[0];
    const int*   ei     = (const int*)  d_in[1];
    const float* root   = (const float*)d_in[3];
    const float* att_l  = (const float*)d_in[4];
    const float* att_r  = (const float*)d_in[5];
    const float* w_ih   = (const float*)d_in[6];
    const float* b_ih   = (const float*)d_in[8];
    const float* b_hh   = (const float*)d_in[9];
    const float* w_fin  = (const float*)d_in[10];
    const float* b_fin  = (const float*)d_in[11];
    const float* w_root = (const float*)d_in[12];
    const float* b_root = (const float*)d_in[13];
    const float* alpha  = (const float*)d_in[14];
    float* out = (float*)d_out;

    int E = in_sizes[1] / 2;
    const int* src0 = ei;
    const int* dst0 = ei + E;

    __half *xh, *h0, *h1;
    int *scoreA, *scoreB, *permA, *permB, *nmapA, *nmapB;
    float2 *pack0, *pack1, *pack2;
    float *al0, *al1, *al2;
    cudaGetSymbolAddress((void**)&xh,     g_xh);
    cudaGetSymbolAddress((void**)&h0,     g_h0);
    cudaGetSymbolAddress((void**)&h1,     g_h1);
    cudaGetSymbolAddress((void**)&scoreA, g_scoreA);
    cudaGetSymbolAddress((void**)&scoreB, g_scoreB);
    cudaGetSymbolAddress((void**)&permA,  g_permA);
    cudaGetSymbolAddress((void**)&permB,  g_permB);
    cudaGetSymbolAddress((void**)&nmapA,  g_nmapA);
    cudaGetSymbolAddress((void**)&nmapB,  g_nmapB);
    cudaGetSymbolAddress((void**)&pack0,  g_pack0);
    cudaGetSymbolAddress((void**)&pack1,  g_pack1);
    cudaGetSymbolAddress((void**)&pack2,  g_pack2);
    cudaGetSymbolAddress((void**)&al0,    g_al0);
    cudaGetSymbolAddress((void**)&al1,    g_al1);
    cudaGetSymbolAddress((void**)&al2,    g_al2);

    static cudaStream_t sA = nullptr, sB = nullptr;
    static cudaEvent_t e0, eNP, eDeg, eScat, eDS1, eDS2;
    if (!sA) {
        cudaStreamCreateWithFlags(&sA, cudaStreamNonBlocking);
        cudaStreamCreateWithFlags(&sB, cudaStreamNonBlocking);
        cudaEventCreateWithFlags(&e0,    cudaEventDisableTiming);
        cudaEventCreateWithFlags(&eNP,   cudaEventDisableTiming);
        cudaEventCreateWithFlags(&eDeg,  cudaEventDisableTiming);
        cudaEventCreateWithFlags(&eScat, cudaEventDisableTiming);
        cudaEventCreateWithFlags(&eDS1,  cudaEventDisableTiming);
        cudaEventCreateWithFlags(&eDS2,  cudaEventDisableTiming);
        cudaFuncSetAttribute(k_rank<16>, cudaFuncAttributeMaxDynamicSharedMemorySize, 70656);
        cudaFuncSetAttribute(k_rank<8>,  cudaFuncAttributeMaxDynamicSharedMemorySize, 70656);
    }
    const int RSMEM = (32*512 + 1024) * 4;

    k_zero<<<512, 256>>>();
    cudaEventRecord(e0, 0);
    cudaStreamWaitEvent(sA, e0, 0);
    k_nodeprep<<<131072 / 8, 256, 0, sA>>>(x, att_l, att_r);
    cudaEventRecord(eNP, sA);

    k_degree <<<1024, 256>>>(src0, dst0, E);
    cudaEventRecord(eDeg, 0);
    k_scan   <<<32, 1024>>>();
    k_scatter<<<1024, 256>>>(src0, dst0, E);
    cudaEventRecord(eScat, 0);

    cudaStreamWaitEvent(0, eNP, 0);
    k_agg<0><<<16384, 256>>>(xh, pack0, al0,
                             al1, pack1, att_l + CC, att_r + CC, h0, 14, 0);

    // side stream B (forked via eDeg): rank + masked degrees, hidden under agg0
    cudaStreamWaitEvent(sB, eDeg, 0);
    k_rank<16><<<G, 1024, RSMEM, sB>>>(scoreA, permA, nmapA, 8192);
    cudaStreamWaitEvent(sB, eScat, 0);
    k_degscore1<<<256, 256, 0, sB>>>();
    cudaEventRecord(eDS1, sB);
    k_rank<8><<<G, 1024, RSMEM, sB>>>(scoreB, permB, nmapB, 4096);
    k_degscore2<<<128, 256, 0, sB>>>();
    cudaEventRecord(eDS2, sB);

    // main: remaining aggregation chain
    cudaStreamWaitEvent(0, eDS1, 0);
    k_agg<1><<<8192, 256>>>(h0, pack1, al1,
                            al2, pack2, att_l + 2*CC, att_r + 2*CC, h1, 13, 1);
    cudaStreamWaitEvent(0, eDS2, 0);
    k_agg<2><<<4096, 256>>>(h1, pack2, al2,
                            nullptr, nullptr, nullptr, nullptr, nullptr, 12, 2);

    k_head<<<G, 256>>>(w_ih, b_ih, b_hh, w_fin, b_fin, w_root, b_root,
                       root, alpha, out);
}

// round 11
// speedup vs baseline: 1.0588x; 1.0588x over previous
#include <cuda_runtime.h>
#include <cuda_fp16.h>

#define G       8
#define CC      128
#define LL      3
#define HH      256
#define EPS_FA  0.1f
#define EMAX    1048576
#define SBINS   512

// ---------------- scratch (device globals; no allocations) ----------------
__device__ __half  g_xh [131072 * CC];         // half copy of original x
__device__ __half  g_h0 [131072 * CC];         // layer-0 h (half), orig-id indexed
__device__ __half  g_h1 [131072 * CC];         // layer-1 h (half), orig-id indexed
__device__ int     g_csr0[EMAX];
__device__ __align__(16) int g_deg0[131072];
__device__ int     g_scoreA[131072], g_scoreB[65536];
__device__ __align__(16) int g_offs0[131072];
__device__ unsigned g_state0[64];
__device__ int     g_nmapA[131072], g_nmapB[65536];
__device__ int     g_permA[65536], g_permB[32768];
__device__ float2  g_pack0[131072];            // {ar0, dinv0}
__device__ float2  g_pack1[131072];            // {ar1, dinv1 or 0 if dropped}
__device__ float2  g_pack2[131072];            // {ar2, dinv2 or 0 if dropped}
__device__ float   g_al0[131072], g_al1[131072], g_al2[131072];
__device__ float   g_pool[LL * G * CC];

__device__ __forceinline__ float2 h2f(unsigned u)
{
    __half2 h = *reinterpret_cast<__half2*>(&u);
    return __half22float2(h);
}

// ---------------- kernels ----------------

__global__ void k_zero()
{
    int i = blockIdx.x * blockDim.x + threadIdx.x;   // 131072 threads
    g_deg0[i] = 0; g_scoreA[i] = 0;
    g_pack1[i] = make_float2(0.f, 0.f);
    g_pack2[i] = make_float2(0.f, 0.f);
    if (i < 65536) g_scoreB[i] = 0;
    if (i < LL * G * CC) g_pool[i] = 0.0f;
    if (i < 64) g_state0[i] = 0u;
}

__global__ void k_degree(const int* __restrict__ src, const int* __restrict__ dst, int E)
{
    int i = blockIdx.x * blockDim.x + threadIdx.x;
    int n4 = E >> 2;
    for (int e = i; e < n4; e += gridDim.x * blockDim.x) {
        int4 d = ((const int4*)dst)[e];
        int4 s = ((const int4*)src)[e];
        atomicAdd(&g_deg0[d.x], 1); atomicAdd(&g_deg0[d.y], 1);
        atomicAdd(&g_deg0[d.z], 1); atomicAdd(&g_deg0[d.w], 1);
        atomicAdd(&g_scoreA[s.x], 1); atomicAdd(&g_scoreA[s.y], 1);
        atomicAdd(&g_scoreA[s.z], 1); atomicAdd(&g_scoreA[s.w], 1);
    }
    // E is a multiple of 4 (G*N0*DEG)
}

// exclusive scan of deg0 (decoupled lookback) + write pack0.y = rsqrt(deg+1)
__global__ void __launch_bounds__(1024, 1) k_scan()
{
    __shared__ int sh[1024];
    __shared__ int s_base;
    int tid = threadIdx.x, b = blockIdx.x;
    int gi = b * 4096 + tid * 4;
    int4 v = *(const int4*)(g_deg0 + gi);
    g_pack0[gi + 0].y = rsqrtf((float)v.x + 1.0f);
    g_pack0[gi + 1].y = rsqrtf((float)v.y + 1.0f);
    g_pack0[gi + 2].y = rsqrtf((float)v.z + 1.0f);
    g_pack0[gi + 3].y = rsqrtf((float)v.w + 1.0f);
    int tsum = v.x + v.y + v.z + v.w;
    sh[tid] = tsum;
    __syncthreads();
    int acc = tsum;
#pragma unroll
    for (int off = 1; off < 1024; off <<= 1) {
        int add = (tid >= off) ? sh[tid - off] : 0;
        __syncthreads();
        acc += add;
        sh[tid] = acc;
        __syncthreads();
    }
    int total = sh[1023];
    if (tid == 0 && b > 0)
        atomicExch(&g_state0[b], 0x40000000u | (unsigned)total);
    if (tid < 32) {
        int base = 0;
        if (b > 0) {
            int idx = b - 1 - tid;
            while (true) {
                unsigned s = 0;
                if (idx >= 0) { do { s = atomicAdd(&g_state0[idx], 0u); } while (s == 0u); }
                unsigned pm = __ballot_sync(0xffffffffu, idx >= 0 && (s & 0x80000000u));
                int firstP = pm ? (__ffs(pm) - 1) : 32;
                int c = (idx >= 0 && tid <= firstP) ? (int)(s & 0x3FFFFFFFu) : 0;
#pragma unroll
                for (int o = 16; o; o >>= 1) c += __shfl_xor_sync(0xffffffffu, c, o);
                base += c;
                if (pm) break;
                idx -= 32;
            }
        }
        if (tid == 0) {
            atomicExch(&g_state0[b], 0x80000000u | (unsigned)(base + total));
            s_base = base;
        }
    }
    __syncthreads();
    int excl = s_base + acc - tsum;
    int4 o;
    o.x = excl; o.y = excl + v.x; o.z = o.y + v.y; o.w = o.z + v.z;
    *(int4*)(g_offs0 + gi) = o;
}

// scatter edges into CSR-by-dst using offs0 itself as the cursor.
// After this kernel offs0[d] == start(d) + deg(d); consumers recompute start.
__global__ void k_scatter(const int* __restrict__ src, const int* __restrict__ dst, int E)
{
    for (int e = blockIdx.x * blockDim.x + threadIdx.x; e < E;
         e += gridDim.x * blockDim.x) {
        int p = atomicAdd(&g_offs0[dst[e]], 1);
        g_csr0[p] = src[e];
    }
}

// layer-0 node prep: pack0.x = ar0, al0, half copy of x
__global__ void k_nodeprep(const float* __restrict__ x,
                           const float* __restrict__ attl, const float* __restrict__ attr)
{
    int warp = (blockIdx.x * blockDim.x + threadIdx.x) >> 5;
    int lane = threadIdx.x & 31;
    float4 cv = __ldg((const float4*)(x + (size_t)warp * CC) + lane);
    float4 lv = ((const float4*)attl)[lane];
    float4 rv = ((const float4*)attr)[lane];
    float al = cv.x*lv.x + cv.y*lv.y + cv.z*lv.z + cv.w*lv.w;
    float ar = cv.x*rv.x + cv.y*rv.y + cv.z*rv.z + cv.w*rv.w;
#pragma unroll
    for (int o = 16; o; o >>= 1) {
        al += __shfl_xor_sync(0xffffffffu, al, o);
        ar += __shfl_xor_sync(0xffffffffu, ar, o);
    }
    if (lane == 0) { g_al0[warp] = al; g_pack0[warp].x = ar; }
    uint2 h;
    *reinterpret_cast<__half2*>(&h.x) = __floats2half2_rn(cv.x, cv.y);
    *reinterpret_cast<__half2*>(&h.y) = __floats2half2_rn(cv.z, cv.w);
    ((uint2*)(g_xh + (size_t)warp * CC))[lane] = h;
}

// unified aggregation (round-9 form): warp per dst node, masked walk of csr0,
// coef via pack (pack.y==0 encodes dropped source). All ids are orig ids.
template<int MODE>
__global__ void __launch_bounds__(256) k_agg(
                      const __half* __restrict__ feat,
                      const float2* __restrict__ pack,
                      const float* __restrict__ alC,
                      float* __restrict__ alN, float2* __restrict__ packN,
                      const float* __restrict__ attlN, const float* __restrict__ attrN,
                      __half* __restrict__ hout, int log2npg, int layer)
{
    __shared__ unsigned smax[128];
    __shared__ int2 spair[8][32];
    int tid  = threadIdx.x;
    int lane = tid & 31;
    int w    = tid >> 5;
    if (tid < 128) smax[tid] = 0;
    __syncthreads();

    int d = (blockIdx.x * blockDim.x + tid) >> 5;
    int old0;
    if (MODE == 0)      old0 = d;
    else if (MODE == 1) old0 = g_permA[d];
    else                old0 = g_permA[g_permB[d]];

    int cnt   = g_deg0[old0];
    int start = g_offs0[old0] - cnt;       // offs0 was advanced by scatter
    float2 pkS = __ldg(&pack[old0]);
    float dind = pkS.y;
    float ald  = alC[old0];

    float4 a = {0.f, 0.f, 0.f, 0.f};
    for (int base = 0; base < cnt; base += 32) {
        int j = base + lane;
        int s0 = 0; float2 sp = make_float2(0.f, 0.f);
        if (j < cnt) {
            s0 = g_csr0[start + j];
            sp = __ldg(&pack[s0]);
        }
        bool valid = (j < cnt) && (sp.y != 0.0f);
        float coef = 0.f;
        if (valid) coef = sp.y * dind * tanhf(ald + sp.x);
        unsigned bal = __ballot_sync(0xffffffffu, valid);
        int m = __popc(bal);
        if (valid) {
            int pos = __popc(bal & ((1u << lane) - 1u));
            spair[w][pos] = make_int2(s0, __float_as_int(coef));
        }
        __syncwarp();
        int t = 0;
        for (; t + 8 <= m; t += 8) {
            uint2 p[8]; float c[8];
#pragma unroll
            for (int q = 0; q < 8; q++) {
                int2 pr = spair[w][t + q];
                c[q] = __int_as_float(pr.y);
                p[q] = __ldg((const uint2*)(feat + (size_t)pr.x * CC) + lane);
            }
#pragma unroll
            for (int q = 0; q < 8; q++) {
                float2 f0 = h2f(p[q].x), f1 = h2f(p[q].y);
                a.x += c[q]*f0.x; a.y += c[q]*f0.y;
                a.z += c[q]*f1.x; a.w += c[q]*f1.y;
            }
        }
        if (t + 4 <= m) {
            uint2 p[4]; float c[4];
#pragma unroll
            for (int q = 0; q < 4; q++) {
                int2 pr = spair[w][t + q];
                c[q] = __int_as_float(pr.y);
                p[q] = __ldg((const uint2*)(feat + (size_t)pr.x * CC) + lane);
            }
#pragma unroll
            for (int q = 0; q < 4; q++) {
                float2 f0 = h2f(p[q].x), f1 = h2f(p[q].y);
                a.x += c[q]*f0.x; a.y += c[q]*f0.y;
                a.z += c[q]*f1.x; a.w += c[q]*f1.y;
            }
            t += 4;
        }
        for (; t < m; t++) {
            int2 pr = spair[w][t];
            float cc = __int_as_float(pr.y);
            uint2 p = __ldg((const uint2*)(feat + (size_t)pr.x * CC) + lane);
            float2 f0 = h2f(p.x), f1 = h2f(p.y);
            a.x += cc*f0.x; a.y += cc*f0.y; a.z += cc*f1.x; a.w += cc*f1.y;
        }
        __syncwarp();
    }

    // self-loop + EPS*orig + relu
    uint2 pc = __ldg((const uint2*)(feat + (size_t)old0 * CC) + lane);
    uint2 po = (MODE == 0) ? pc
             : __ldg((const uint2*)(g_xh + (size_t)old0 * CC) + lane);
    float2 c01 = h2f(pc.x), c23 = h2f(pc.y);
    float2 o01 = h2f(po.x), o23 = h2f(po.y);
    float c0 = dind * dind * tanhf(ald + pkS.x);
    a.x = fmaxf(c0*c01.x + EPS_FA*o01.x + a.x, 0.f);
    a.y = fmaxf(c0*c01.y + EPS_FA*o01.y + a.y, 0.f);
    a.z = fmaxf(c0*c23.x + EPS_FA*o23.x + a.z, 0.f);
    a.w = fmaxf(c0*c23.y + EPS_FA*o23.y + a.w, 0.f);

    if (MODE < 2) {
        uint2 hh;
        *reinterpret_cast<__half2*>(&hh.x) = __floats2half2_rn(a.x, a.y);
        *reinterpret_cast<__half2*>(&hh.y) = __floats2half2_rn(a.z, a.w);
        ((uint2*)(hout + (size_t)old0 * CC))[lane] = hh;
        float4 lv = ((const float4*)attlN)[lane];
        float4 rv = ((const float4*)attrN)[lane];
        float aln = a.x*lv.x + a.y*lv.y + a.z*lv.z + a.w*lv.w;
        float arn = a.x*rv.x + a.y*rv.y + a.z*rv.z + a.w*rv.w;
#pragma unroll
        for (int o = 16; o; o >>= 1) {
            aln += __shfl_xor_sync(0xffffffffu, aln, o);
            arn += __shfl_xor_sync(0xffffffffu, arn, o);
        }
        if (lane == 0) { alN[old0] = aln; packN[old0].x = arn; }
    }

    atomicMax(&smax[lane*4 + 0], __float_as_uint(a.x));
    atomicMax(&smax[lane*4 + 1], __float_as_uint(a.y));
    atomicMax(&smax[lane*4 + 2], __float_as_uint(a.z));
    atomicMax(&smax[lane*4 + 3], __float_as_uint(a.w));
    __syncthreads();
    if (tid < 128) {
        int g = (int)((blockIdx.x * (blockDim.x >> 5)) >> log2npg);
        atomicMax((unsigned*)&g_pool[(layer * G + g) * CC + tid], smax[tid]);
    }
}

// fused exact stable top-k (counting rank), one block per graph, 1024 threads.
template<int ROUNDS>
__global__ void __launch_bounds__(1024, 1) k_rank(
                       const int* __restrict__ score, int* __restrict__ perm,
                       int* __restrict__ nmap, int kk)
{
    extern __shared__ int smem[];
    int* whist = smem;              // 32*512
    int* s_tot = smem + 32*512;     // 512
    int* s_cnt = s_tot + 512;       // 512
    int tid = threadIdx.x, w = tid >> 5, lane = tid & 31;
    int npg = ROUNDS * 1024;
    int nbase = blockIdx.x * npg + w * (ROUNDS * 32);

    for (int i = lane; i < 512; i += 32) whist[w*512 + i] = 0;
    __syncwarp();

    int seq[ROUNDS];
#pragma unroll
    for (int r = 0; r < ROUNDS; r++) {
        int i = nbase + r * 32 + lane;
        int s = min(score[i], SBINS - 1);
        unsigned mk = __match_any_sync(0xffffffffu, s);
        int intra = __popc(mk & ((1u << lane) - 1u));
        int cur = whist[w*512 + s];
        __syncwarp();
        if (intra == 0) whist[w*512 + s] = cur + __popc(mk);
        __syncwarp();
        seq[r] = cur + intra;
    }
    __syncthreads();

    if (tid < 512) {
        int run = 0;
        for (int ww = 0; ww < 32; ww++) {
            int v = whist[ww*512 + tid];
            whist[ww*512 + tid] = run;
            run += v;
        }
        s_tot[tid] = run;
        s_cnt[tid] = run;
    }
    __syncthreads();
    for (int off = 1; off < 512; off <<= 1) {
        int add = 0;
        if (tid < 512 && tid + off < 512) add = s_cnt[tid + off];
        __syncthreads();
        if (tid < 512) s_cnt[tid] += add;
        __syncthreads();
    }

#pragma unroll
    for (int r = 0; r < ROUNDS; r++) {
        int i = nbase + r * 32 + lane;
        int s = min(score[i], SBINS - 1);
        int rank = (s_cnt[s] - s_tot[s]) + whist[w*512 + s] + seq[r];
        int nm = -1;
        if (rank < kk) {
            int neu = blockIdx.x * kk + rank;
            perm[neu] = i;
            nm = neu;
        }
        nmap[i] = nm;
    }
}

// layer-1 masked degree + out-degree score + pack1.y
__global__ void k_degscore1()
{
    int j = blockIdx.x * blockDim.x + threadIdx.x;   // 0..65535
    int old0 = g_permA[j];
    int c = g_deg0[old0];
    int st = g_offs0[old0] - c;
    int dcur = 0;
    for (int k = 0; k < c; k++) {
        int s0 = g_csr0[st + k];
        int s1 = g_nmapA[s0];
        if (s1 >= 0) { dcur++; atomicAdd(&g_scoreB[s1], 1); }
    }
    g_pack1[old0].y = rsqrtf((float)dcur + 1.0f);
}

// layer-2 masked degree + pack2.y
__global__ void k_degscore2()
{
    int m = blockIdx.x * blockDim.x + threadIdx.x;   // 0..32767
    int old1 = g_permB[m];
    int old0 = g_permA[old1];
    int c = g_deg0[old0];
    int st = g_offs0[old0] - c;
    int dcur = 0;
    for (int k = 0; k < c; k++) {
        int s0 = g_csr0[st + k];
        int s1 = g_nmapA[s0];
        if (s1 >= 0 && g_nmapB[s1] >= 0) dcur++;
    }
    g_pack2[old0].y = rsqrtf((float)dcur + 1.0f);
}

// GRU (h0=0) + final linears + root residual
__global__ void k_head(const float* __restrict__ w_ih, const float* __restrict__ b_ih,
                       const float* __restrict__ b_hh,
                       const float* __restrict__ w_fin, const float* __restrict__ b_fin,
                       const float* __restrict__ w_root, const float* __restrict__ b_root,
                       const float* __restrict__ root, const float* __restrict__ alpha_p,
                       float* __restrict__ out)
{
    __shared__ float fused[LL * CC];
    __shared__ float hgru[HH];
    __shared__ float rootv[CC];
    int g = blockIdx.x, t = threadIdx.x;
    for (int i = t; i < LL * CC; i += 256) {
        int layer = i >> 7, c = i & 127;
        fused[i] = g_pool[layer * G * CC + g * CC + c];
    }
    if (t < CC) rootv[t] = root[g * CC + t];
    __syncthreads();

    float gr = b_ih[t], gz = b_ih[HH + t], gn = b_ih[2 * HH + t];
    const float* wr = w_ih + (size_t)t            * (LL * CC);
    const float* wz = w_ih + (size_t)(HH + t)     * (LL * CC);
    const float* wn = w_ih + (size_t)(2 * HH + t) * (LL * CC);
    for (int j = 0; j < LL * CC; j++) {
        float f = fused[j];
        gr += wr[j] * f; gz += wz[j] * f; gn += wn[j] * f;
    }
    float r  = 1.0f / (1.0f + expf(-(gr + b_hh[t])));
    float z  = 1.0f / (1.0f + expf(-(gz + b_hh[HH + t])));
    float nc = tanhf(gn + r * b_hh[2 * HH + t]);
    hgru[t] = (1.0f - z) * nc;
    __syncthreads();

    if (t < CC) {
        float acc = b_fin[t];
        const float* wf = w_fin + (size_t)t * HH;
        for (int j = 0; j < HH; j++) acc += wf[j] * hgru[j];
        float re = b_root[t];
        const float* wo = w_root + (size_t)t * CC;
        for (int j = 0; j < CC; j++) re += wo[j] * rootv[j];
        float a = *alpha_p;
        out[g * CC + t] = a * acc + (1.0f - a) * re;
    }
}

// ---------------- launch ----------------

extern "C" void kernel_launch(void* const* d_in, const int* in_sizes, int n_in,
                              void* d_out, int out_size)
{
    const float* x      = (const float*)d_in[0];
    const int*   ei     = (const int*)  d_in[1];
    const float* root   = (const float*)d_in[3];
    const float* att_l  = (const float*)d_in[4];
    const float* att_r  = (const float*)d_in[5];
    const float* w_ih   = (const float*)d_in[6];
    const float* b_ih   = (const float*)d_in[8];
    const float* b_hh   = (const float*)d_in[9];
    const float* w_fin  = (const float*)d_in[10];
    const float* b_fin  = (const float*)d_in[11];
    const float* w_root = (const float*)d_in[12];
    const float* b_root = (const float*)d_in[13];
    const float* alpha  = (const float*)d_in[14];
    float* out = (float*)d_out;

    int E = in_sizes[1] / 2;
    const int* src0 = ei;
    const int* dst0 = ei + E;

    __half *xh, *h0, *h1;
    int *scoreA, *scoreB, *permA, *permB, *nmapA, *nmapB;
    float2 *pack0, *pack1, *pack2;
    float *al0, *al1, *al2;
    cudaGetSymbolAddress((void**)&xh,     g_xh);
    cudaGetSymbolAddress((void**)&h0,     g_h0);
    cudaGetSymbolAddress((void**)&h1,     g_h1);
    cudaGetSymbolAddress((void**)&scoreA, g_scoreA);
    cudaGetSymbolAddress((void**)&scoreB, g_scoreB);
    cudaGetSymbolAddress((void**)&permA,  g_permA);
    cudaGetSymbolAddress((void**)&permB,  g_permB);
    cudaGetSymbolAddress((void**)&nmapA,  g_nmapA);
    cudaGetSymbolAddress((void**)&nmapB,  g_nmapB);
    cudaGetSymbolAddress((void**)&pack0,  g_pack0);
    cudaGetSymbolAddress((void**)&pack1,  g_pack1);
    cudaGetSymbolAddress((void**)&pack2,  g_pack2);
    cudaGetSymbolAddress((void**)&al0,    g_al0);
    cudaGetSymbolAddress((void**)&al1,    g_al1);
    cudaGetSymbolAddress((void**)&al2,    g_al2);

    static cudaStream_t sA = nullptr, sB = nullptr;
    static cudaEvent_t e0, eNP, eDeg, eScat, eDS1, eDS2;
    if (!sA) {
        cudaStreamCreateWithFlags(&sA, cudaStreamNonBlocking);
        cudaStreamCreateWithFlags(&sB, cudaStreamNonBlocking);
        cudaEventCreateWithFlags(&e0,    cudaEventDisableTiming);
        cudaEventCreateWithFlags(&eNP,   cudaEventDisableTiming);
        cudaEventCreateWithFlags(&eDeg,  cudaEventDisableTiming);
        cudaEventCreateWithFlags(&eScat, cudaEventDisableTiming);
        cudaEventCreateWithFlags(&eDS1,  cudaEventDisableTiming);
        cudaEventCreateWithFlags(&eDS2,  cudaEventDisableTiming);
        cudaFuncSetAttribute(k_rank<16>, cudaFuncAttributeMaxDynamicSharedMemorySize, 70656);
        cudaFuncSetAttribute(k_rank<8>,  cudaFuncAttributeMaxDynamicSharedMemorySize, 70656);
    }
    const int RSMEM = (32*512 + 1024) * 4;

    k_zero<<<512, 256>>>();
    cudaEventRecord(e0, 0);
    cudaStreamWaitEvent(sA, e0, 0);
    k_nodeprep<<<131072 / 8, 256, 0, sA>>>(x, att_l, att_r);
    cudaEventRecord(eNP, sA);

    k_degree <<<1024, 256>>>(src0, dst0, E);
    cudaEventRecord(eDeg, 0);
    k_scan   <<<32, 1024>>>();
    k_scatter<<<1024, 256>>>(src0, dst0, E);
    cudaEventRecord(eScat, 0);

    cudaStreamWaitEvent(0, eNP, 0);
    k_agg<0><<<16384, 256>>>(xh, pack0, al0,
                             al1, pack1, att_l + CC, att_r + CC, h0, 14, 0);

    // side stream B (forked via eDeg): rank + masked degrees, hidden under agg0
    cudaStreamWaitEvent(sB, eDeg, 0);
    k_rank<16><<<G, 1024, RSMEM, sB>>>(scoreA, permA, nmapA, 8192);
    cudaStreamWaitEvent(sB, eScat, 0);
    k_degscore1<<<256, 256, 0, sB>>>();
    cudaEventRecord(eDS1, sB);
    k_rank<8><<<G, 1024, RSMEM, sB>>>(scoreB, permB, nmapB, 4096);
    k_degscore2<<<128, 256, 0, sB>>>();
    cudaEventRecord(eDS2, sB);

    // main: remaining aggregation chain
    cudaStreamWaitEvent(0, eDS1, 0);
    k_agg<1><<<8192, 256>>>(h0, pack1, al1,
                            al2, pack2, att_l + 2*CC, att_r + 2*CC, h1, 13, 1);
    cudaStreamWaitEvent(0, eDS2, 0);
    k_agg<2><<<4096, 256>>>(h1, pack2, al2,
                            nullptr, nullptr, nullptr, nullptr, nullptr, 12, 2);

    k_head<<<G, 256>>>(w_ih, b_ih, b_hh, w_fin, b_fin, w_root, b_root,
                       root, alpha, out);
}

// round 12
// speedup vs baseline: 1.0658x; 1.0066x over previous
#include <cuda_runtime.h>
#include <cuda_fp16.h>

#define G       8
#define CC      128
#define LL      3
#define HH      256
#define EPS_FA  0.1f
#define EMAX    1048576
#define SBINS   512
#define NB_DEG  1024           // blocks of k_prep doing edge degree

// ---------------- scratch (device globals; no allocations) ----------------
// NOTE: all zero-initialized at module load; k_cleanup restores the zeros each
// replay so the graph is replay-deterministic.
__device__ __half  g_xh [131072 * CC];         // half copy of original x
__device__ __half  g_h0 [131072 * CC];         // layer-0 h (half), orig-id indexed
__device__ __half  g_h1 [131072 * CC];         // layer-1 h (half), orig-id indexed
__device__ int     g_csr0[EMAX];
__device__ __align__(16) int g_deg0[131072];
__device__ int     g_scoreA[131072], g_scoreB[65536];
__device__ __align__(16) int g_offs0[131072];
__device__ unsigned g_state0[64];
__device__ int     g_nmapA[131072], g_nmapB[65536];
__device__ int     g_permA[65536], g_permB[32768];
__device__ float2  g_pack0[131072];            // {ar0, dinv0}
__device__ float2  g_pack1[131072];            // {ar1, dinv1 or 0 if dropped}
__device__ float2  g_pack2[131072];            // {ar2, dinv2 or 0 if dropped}
__device__ float   g_al0[131072], g_al1[131072], g_al2[131072];
__device__ float   g_pool[LL * G * CC];

__device__ __forceinline__ float2 h2f(unsigned u)
{
    __half2 h = *reinterpret_cast<__half2*>(&u);
    return __half22float2(h);
}

// ---------------- kernels ----------------

// fused: blocks [0,NB_DEG) do edge degree/score atomics; the rest do node prep
// (al0/ar0 dots + half copy of x). Both halves only read inputs; they are
// independent and overlap within one launch.
__global__ void k_prep(const int* __restrict__ src, const int* __restrict__ dst, int E,
                       const float* __restrict__ x,
                       const float* __restrict__ attl, const float* __restrict__ attr)
{
    if (blockIdx.x < NB_DEG) {
        int i = blockIdx.x * blockDim.x + threadIdx.x;
        int n4 = E >> 2;                          // E multiple of 4
        for (int e = i; e < n4; e += NB_DEG * blockDim.x) {
            int4 d = ((const int4*)dst)[e];
            int4 s = ((const int4*)src)[e];
            atomicAdd(&g_deg0[d.x], 1); atomicAdd(&g_deg0[d.y], 1);
            atomicAdd(&g_deg0[d.z], 1); atomicAdd(&g_deg0[d.w], 1);
            atomicAdd(&g_scoreA[s.x], 1); atomicAdd(&g_scoreA[s.y], 1);
            atomicAdd(&g_scoreA[s.z], 1); atomicAdd(&g_scoreA[s.w], 1);
        }
    } else {
        int warp = (((int)blockIdx.x - NB_DEG) * blockDim.x + threadIdx.x) >> 5;
        int lane = threadIdx.x & 31;
        float4 cv = __ldg((const float4*)(x + (size_t)warp * CC) + lane);
        float4 lv = ((const float4*)attl)[lane];
        float4 rv = ((const float4*)attr)[lane];
        float al = cv.x*lv.x + cv.y*lv.y + cv.z*lv.z + cv.w*lv.w;
        float ar = cv.x*rv.x + cv.y*rv.y + cv.z*rv.z + cv.w*rv.w;
#pragma unroll
        for (int o = 16; o; o >>= 1) {
            al += __shfl_xor_sync(0xffffffffu, al, o);
            ar += __shfl_xor_sync(0xffffffffu, ar, o);
        }
        if (lane == 0) { g_al0[warp] = al; g_pack0[warp].x = ar; }
        uint2 h;
        *reinterpret_cast<__half2*>(&h.x) = __floats2half2_rn(cv.x, cv.y);
        *reinterpret_cast<__half2*>(&h.y) = __floats2half2_rn(cv.z, cv.w);
        ((uint2*)(g_xh + (size_t)warp * CC))[lane] = h;
    }
}

// exclusive scan of deg0 (decoupled lookback) + write pack0.y = rsqrt(deg+1)
__global__ void __launch_bounds__(1024, 1) k_scan()
{
    __shared__ int sh[1024];
    __shared__ int s_base;
    int tid = threadIdx.x, b = blockIdx.x;
    int gi = b * 4096 + tid * 4;
    int4 v = *(const int4*)(g_deg0 + gi);
    g_pack0[gi + 0].y = rsqrtf((float)v.x + 1.0f);
    g_pack0[gi + 1].y = rsqrtf((float)v.y + 1.0f);
    g_pack0[gi + 2].y = rsqrtf((float)v.z + 1.0f);
    g_pack0[gi + 3].y = rsqrtf((float)v.w + 1.0f);
    int tsum = v.x + v.y + v.z + v.w;
    sh[tid] = tsum;
    __syncthreads();
    int acc = tsum;
#pragma unroll
    for (int off = 1; off < 1024; off <<= 1) {
        int add = (tid >= off) ? sh[tid - off] : 0;
        __syncthreads();
        acc += add;
        sh[tid] = acc;
        __syncthreads();
    }
    int total = sh[1023];
    if (tid == 0 && b > 0)
        atomicExch(&g_state0[b], 0x40000000u | (unsigned)total);
    if (tid < 32) {
        int base = 0;
        if (b > 0) {
            int idx = b - 1 - tid;
            while (true) {
                unsigned s = 0;
                if (idx >= 0) { do { s = atomicAdd(&g_state0[idx], 0u); } while (s == 0u); }
                unsigned pm = __ballot_sync(0xffffffffu, idx >= 0 && (s & 0x80000000u));
                int firstP = pm ? (__ffs(pm) - 1) : 32;
                int c = (idx >= 0 && tid <= firstP) ? (int)(s & 0x3FFFFFFFu) : 0;
#pragma unroll
                for (int o = 16; o; o >>= 1) c += __shfl_xor_sync(0xffffffffu, c, o);
                base += c;
                if (pm) break;
                idx -= 32;
            }
        }
        if (tid == 0) {
            atomicExch(&g_state0[b], 0x80000000u | (unsigned)(base + total));
            s_base = base;
        }
    }
    __syncthreads();
    int excl = s_base + acc - tsum;
    int4 o;
    o.x = excl; o.y = excl + v.x; o.z = o.y + v.y; o.w = o.z + v.z;
    *(int4*)(g_offs0 + gi) = o;
}

// scatter edges into CSR-by-dst using offs0 itself as the cursor.
// After this kernel offs0[d] == start(d) + deg(d); consumers recompute start.
__global__ void k_scatter(const int* __restrict__ src, const int* __restrict__ dst, int E)
{
    for (int e = blockIdx.x * blockDim.x + threadIdx.x; e < E;
         e += gridDim.x * blockDim.x) {
        int p = atomicAdd(&g_offs0[dst[e]], 1);
        g_csr0[p] = src[e];
    }
}

// unified aggregation: warp per dst node, masked walk of csr0, coef via pack
// (pack.y==0 encodes dropped source). All ids are orig ids.
template<int MODE>
__global__ void __launch_bounds__(256) k_agg(
                      const __half* __restrict__ feat,
                      const float2* __restrict__ pack,
                      const float* __restrict__ alC,
                      float* __restrict__ alN, float2* __restrict__ packN,
                      const float* __restrict__ attlN, const float* __restrict__ attrN,
                      __half* __restrict__ hout, int log2npg, int layer)
{
    __shared__ unsigned smax[128];
    __shared__ int2 spair[8][32];
    int tid  = threadIdx.x;
    int lane = tid & 31;
    int w    = tid >> 5;
    if (tid < 128) smax[tid] = 0;
    __syncthreads();

    int d = (blockIdx.x * blockDim.x + tid) >> 5;
    int old0;
    if (MODE == 0)      old0 = d;
    else if (MODE == 1) old0 = g_permA[d];
    else                old0 = g_permA[g_permB[d]];

    int cnt   = g_deg0[old0];
    int start = g_offs0[old0] - cnt;       // offs0 was advanced by scatter
    float2 pkS = __ldg(&pack[old0]);
    float dind = pkS.y;
    float ald  = alC[old0];

    float4 a = {0.f, 0.f, 0.f, 0.f};
    for (int base = 0; base < cnt; base += 32) {
        int j = base + lane;
        int s0 = 0; float2 sp = make_float2(0.f, 0.f);
        if (j < cnt) {
            s0 = g_csr0[start + j];
            sp = __ldg(&pack[s0]);
        }
        bool valid = (j < cnt) && (sp.y != 0.0f);
        float coef = 0.f;
        if (valid) coef = sp.y * dind * tanhf(ald + sp.x);
        unsigned bal = __ballot_sync(0xffffffffu, valid);
        int m = __popc(bal);
        if (valid) {
            int pos = __popc(bal & ((1u << lane) - 1u));
            spair[w][pos] = make_int2(s0, __float_as_int(coef));
        }
        __syncwarp();
        int t = 0;
        for (; t + 8 <= m; t += 8) {
            uint2 p[8]; float c[8];
#pragma unroll
            for (int q = 0; q < 8; q++) {
                int2 pr = spair[w][t + q];
                c[q] = __int_as_float(pr.y);
                p[q] = __ldg((const uint2*)(feat + (size_t)pr.x * CC) + lane);
            }
#pragma unroll
            for (int q = 0; q < 8; q++) {
                float2 f0 = h2f(p[q].x), f1 = h2f(p[q].y);
                a.x += c[q]*f0.x; a.y += c[q]*f0.y;
                a.z += c[q]*f1.x; a.w += c[q]*f1.y;
            }
        }
        if (t + 4 <= m) {
            uint2 p[4]; float c[4];
#pragma unroll
            for (int q = 0; q < 4; q++) {
                int2 pr = spair[w][t + q];
                c[q] = __int_as_float(pr.y);
                p[q] = __ldg((const uint2*)(feat + (size_t)pr.x * CC) + lane);
            }
#pragma unroll
            for (int q = 0; q < 4; q++) {
                float2 f0 = h2f(p[q].x), f1 = h2f(p[q].y);
                a.x += c[q]*f0.x; a.y += c[q]*f0.y;
                a.z += c[q]*f1.x; a.w += c[q]*f1.y;
            }
            t += 4;
        }
        for (; t < m; t++) {
            int2 pr = spair[w][t];
            float cc = __int_as_float(pr.y);
            uint2 p = __ldg((const uint2*)(feat + (size_t)pr.x * CC) + lane);
            float2 f0 = h2f(p.x), f1 = h2f(p.y);
            a.x += cc*f0.x; a.y += cc*f0.y; a.z += cc*f1.x; a.w += cc*f1.y;
        }
        __syncwarp();
    }

    // self-loop + EPS*orig + relu
    uint2 pc = __ldg((const uint2*)(feat + (size_t)old0 * CC) + lane);
    uint2 po = (MODE == 0) ? pc
             : __ldg((const uint2*)(g_xh + (size_t)old0 * CC) + lane);
    float2 c01 = h2f(pc.x), c23 = h2f(pc.y);
    float2 o01 = h2f(po.x), o23 = h2f(po.y);
    float c0 = dind * dind * tanhf(ald + pkS.x);
    a.x = fmaxf(c0*c01.x + EPS_FA*o01.x + a.x, 0.f);
    a.y = fmaxf(c0*c01.y + EPS_FA*o01.y + a.y, 0.f);
    a.z = fmaxf(c0*c23.x + EPS_FA*o23.x + a.z, 0.f);
    a.w = fmaxf(c0*c23.y + EPS_FA*o23.y + a.w, 0.f);

    if (MODE < 2) {
        uint2 hh;
        *reinterpret_cast<__half2*>(&hh.x) = __floats2half2_rn(a.x, a.y);
        *reinterpret_cast<__half2*>(&hh.y) = __floats2half2_rn(a.z, a.w);
        ((uint2*)(hout + (size_t)old0 * CC))[lane] = hh;
        float4 lv = ((const float4*)attlN)[lane];
        float4 rv = ((const float4*)attrN)[lane];
        float aln = a.x*lv.x + a.y*lv.y + a.z*lv.z + a.w*lv.w;
        float arn = a.x*rv.x + a.y*rv.y + a.z*rv.z + a.w*rv.w;
#pragma unroll
        for (int o = 16; o; o >>= 1) {
            aln += __shfl_xor_sync(0xffffffffu, aln, o);
            arn += __shfl_xor_sync(0xffffffffu, arn, o);
        }
        if (lane == 0) { alN[old0] = aln; packN[old0].x = arn; }
    }

    atomicMax(&smax[lane*4 + 0], __float_as_uint(a.x));
    atomicMax(&smax[lane*4 + 1], __float_as_uint(a.y));
    atomicMax(&smax[lane*4 + 2], __float_as_uint(a.z));
    atomicMax(&smax[lane*4 + 3], __float_as_uint(a.w));
    __syncthreads();
    if (tid < 128) {
        int g = (int)((blockIdx.x * (blockDim.x >> 5)) >> log2npg);
        atomicMax((unsigned*)&g_pool[(layer * G + g) * CC + tid], smax[tid]);
    }
}

// fused exact stable top-k (counting rank), one block per graph, 1024 threads.
template<int ROUNDS>
__global__ void __launch_bounds__(1024, 1) k_rank(
                       const int* __restrict__ score, int* __restrict__ perm,
                       int* __restrict__ nmap, int kk)
{
    extern __shared__ int smem[];
    int* whist = smem;              // 32*512
    int* s_tot = smem + 32*512;     // 512
    int* s_cnt = s_tot + 512;       // 512
    int tid = threadIdx.x, w = tid >> 5, lane = tid & 31;
    int npg = ROUNDS * 1024;
    int nbase = blockIdx.x * npg + w * (ROUNDS * 32);

    for (int i = lane; i < 512; i += 32) whist[w*512 + i] = 0;
    __syncwarp();

    int seq[ROUNDS];
#pragma unroll
    for (int r = 0; r < ROUNDS; r++) {
        int i = nbase + r * 32 + lane;
        int s = min(score[i], SBINS - 1);
        unsigned mk = __match_any_sync(0xffffffffu, s);
        int intra = __popc(mk & ((1u << lane) - 1u));
        int cur = whist[w*512 + s];
        __syncwarp();
        if (intra == 0) whist[w*512 + s] = cur + __popc(mk);
        __syncwarp();
        seq[r] = cur + intra;
    }
    __syncthreads();

    if (tid < 512) {
        int run = 0;
        for (int ww = 0; ww < 32; ww++) {
            int v = whist[ww*512 + tid];
            whist[ww*512 + tid] = run;
            run += v;
        }
        s_tot[tid] = run;
        s_cnt[tid] = run;
    }
    __syncthreads();
    for (int off = 1; off < 512; off <<= 1) {
        int add = 0;
        if (tid < 512 && tid + off < 512) add = s_cnt[tid + off];
        __syncthreads();
        if (tid < 512) s_cnt[tid] += add;
        __syncthreads();
    }

#pragma unroll
    for (int r = 0; r < ROUNDS; r++) {
        int i = nbase + r * 32 + lane;
        int s = min(score[i], SBINS - 1);
        int rank = (s_cnt[s] - s_tot[s]) + whist[w*512 + s] + seq[r];
        int nm = -1;
        if (rank < kk) {
            int neu = blockIdx.x * kk + rank;
            perm[neu] = i;
            nm = neu;
        }
        nmap[i] = nm;
    }
}

// layer-1 masked degree + out-degree score + pack1.y
__global__ void k_degscore1()
{
    int j = blockIdx.x * blockDim.x + threadIdx.x;   // 0..65535
    int old0 = g_permA[j];
    int c = g_deg0[old0];
    int st = g_offs0[old0] - c;
    int dcur = 0;
    for (int k = 0; k < c; k++) {
        int s0 = g_csr0[st + k];
        int s1 = g_nmapA[s0];
        if (s1 >= 0) { dcur++; atomicAdd(&g_scoreB[s1], 1); }
    }
    g_pack1[old0].y = rsqrtf((float)dcur + 1.0f);
}

// layer-2 masked degree + pack2.y
__global__ void k_degscore2()
{
    int m = blockIdx.x * blockDim.x + threadIdx.x;   // 0..32767
    int old1 = g_permB[m];
    int old0 = g_permA[old1];
    int c = g_deg0[old0];
    int st = g_offs0[old0] - c;
    int dcur = 0;
    for (int k = 0; k < c; k++) {
        int s0 = g_csr0[st + k];
        int s1 = g_nmapA[s0];
        if (s1 >= 0 && g_nmapB[s1] >= 0) dcur++;
    }
    g_pack2[old0].y = rsqrtf((float)dcur + 1.0f);
}

// restore the zero-invariants for the next graph replay (after last use)
__global__ void k_cleanup()
{
    int i = blockIdx.x * blockDim.x + threadIdx.x;   // 131072 threads
    g_deg0[i] = 0; g_scoreA[i] = 0;
    g_pack1[i] = make_float2(0.f, 0.f);
    g_pack2[i] = make_float2(0.f, 0.f);
    if (i < 65536) g_scoreB[i] = 0;
    if (i < 64) g_state0[i] = 0u;
}

// GRU (h0=0) + final linears + root residual; zeroes g_pool after reading it
__global__ void k_head(const float* __restrict__ w_ih, const float* __restrict__ b_ih,
                       const float* __restrict__ b_hh,
                       const float* __restrict__ w_fin, const float* __restrict__ b_fin,
                       const float* __restrict__ w_root, const float* __restrict__ b_root,
                       const float* __restrict__ root, const float* __restrict__ alpha_p,
                       float* __restrict__ out)
{
    __shared__ float fused[LL * CC];
    __shared__ float hgru[HH];
    __shared__ float rootv[CC];
    int g = blockIdx.x, t = threadIdx.x;
    for (int i = t; i < LL * CC; i += 256) {
        int layer = i >> 7, c = i & 127;
        fused[i] = g_pool[layer * G * CC + g * CC + c];
    }
    if (t < CC) rootv[t] = root[g * CC + t];
    __syncthreads();
    // pool consumed into smem; zero this graph's rows for the next replay
    for (int i = t; i < LL * CC; i += 256) {
        int layer = i >> 7, c = i & 127;
        g_pool[layer * G * CC + g * CC + c] = 0.0f;
    }

    float gr = b_ih[t], gz = b_ih[HH + t], gn = b_ih[2 * HH + t];
    const float* wr = w_ih + (size_t)t            * (LL * CC);
    const float* wz = w_ih + (size_t)(HH + t)     * (LL * CC);
    const float* wn = w_ih + (size_t)(2 * HH + t) * (LL * CC);
    for (int j = 0; j < LL * CC; j++) {
        float f = fused[j];
        gr += wr[j] * f; gz += wz[j] * f; gn += wn[j] * f;
    }
    float r  = 1.0f / (1.0f + expf(-(gr + b_hh[t])));
    float z  = 1.0f / (1.0f + expf(-(gz + b_hh[HH + t])));
    float nc = tanhf(gn + r * b_hh[2 * HH + t]);
    hgru[t] = (1.0f - z) * nc;
    __syncthreads();

    if (t < CC) {
        float acc = b_fin[t];
        const float* wf = w_fin + (size_t)t * HH;
        for (int j = 0; j < HH; j++) acc += wf[j] * hgru[j];
        float re = b_root[t];
        const float* wo = w_root + (size_t)t * CC;
        for (int j = 0; j < CC; j++) re += wo[j] * rootv[j];
        float a = *alpha_p;
        out[g * CC + t] = a * acc + (1.0f - a) * re;
    }
}

// ---------------- launch ----------------

extern "C" void kernel_launch(void* const* d_in, const int* in_sizes, int n_in,
                              void* d_out, int out_size)
{
    const float* x      = (const float*)d_in[0];
    const int*   ei     = (const int*)  d_in[1];
    const float* root   = (const float*)d_in[3];
    const float* att_l  = (const float*)d_in[4];
    const float* att_r  = (const float*)d_in[5];
    const float* w_ih   = (const float*)d_in[6];
    const float* b_ih   = (const float*)d_in[8];
    const float* b_hh   = (const float*)d_in[9];
    const float* w_fin  = (const float*)d_in[10];
    const float* b_fin  = (const float*)d_in[11];
    const float* w_root = (const float*)d_in[12];
    const float* b_root = (const float*)d_in[13];
    const float* alpha  = (const float*)d_in[14];
    float* out = (float*)d_out;

    int E = in_sizes[1] / 2;
    const int* src0 = ei;
    const int* dst0 = ei + E;

    __half *xh, *h0, *h1;
    int *scoreA, *scoreB, *permA, *permB, *nmapA, *nmapB;
    float2 *pack0, *pack1, *pack2;
    float *al0, *al1, *al2;
    cudaGetSymbolAddress((void**)&xh,     g_xh);
    cudaGetSymbolAddress((void**)&h0,     g_h0);
    cudaGetSymbolAddress((void**)&h1,     g_h1);
    cudaGetSymbolAddress((void**)&scoreA, g_scoreA);
    cudaGetSymbolAddress((void**)&scoreB, g_scoreB);
    cudaGetSymbolAddress((void**)&permA,  g_permA);
    cudaGetSymbolAddress((void**)&permB,  g_permB);
    cudaGetSymbolAddress((void**)&nmapA,  g_nmapA);
    cudaGetSymbolAddress((void**)&nmapB,  g_nmapB);
    cudaGetSymbolAddress((void**)&pack0,  g_pack0);
    cudaGetSymbolAddress((void**)&pack1,  g_pack1);
    cudaGetSymbolAddress((void**)&pack2,  g_pack2);
    cudaGetSymbolAddress((void**)&al0,    g_al0);
    cudaGetSymbolAddress((void**)&al1,    g_al1);
    cudaGetSymbolAddress((void**)&al2,    g_al2);

    static cudaStream_t sB = nullptr;
    static cudaEvent_t eP, eScat, eDS1, eDS2, eA2, eCl;
    if (!sB) {
        cudaStreamCreateWithFlags(&sB, cudaStreamNonBlocking);
        cudaEventCreateWithFlags(&eP,    cudaEventDisableTiming);
        cudaEventCreateWithFlags(&eScat, cudaEventDisableTiming);
        cudaEventCreateWithFlags(&eDS1,  cudaEventDisableTiming);
        cudaEventCreateWithFlags(&eDS2,  cudaEventDisableTiming);
        cudaEventCreateWithFlags(&eA2,   cudaEventDisableTiming);
        cudaEventCreateWithFlags(&eCl,   cudaEventDisableTiming);
        cudaFuncSetAttribute(k_rank<16>, cudaFuncAttributeMaxDynamicSharedMemorySize, 70656);
        cudaFuncSetAttribute(k_rank<8>,  cudaFuncAttributeMaxDynamicSharedMemorySize, 70656);
    }
    const int RSMEM = (32*512 + 1024) * 4;

    // main: prep(degree+nodeprep) -> scan -> scatter -> agg0 (4th launch)
    k_prep   <<<NB_DEG + 16384, 256>>>(src0, dst0, E, x, att_l, att_r);
    cudaEventRecord(eP, 0);
    k_scan   <<<32, 1024>>>();
    k_scatter<<<1024, 256>>>(src0, dst0, E);
    cudaEventRecord(eScat, 0);
    k_agg<0><<<16384, 256>>>(xh, pack0, al0,
                             al1, pack1, att_l + CC, att_r + CC, h0, 14, 0);

    // side stream B (forked via eP): rank + masked degrees, hidden under agg0
    cudaStreamWaitEvent(sB, eP, 0);
    k_rank<16><<<G, 1024, RSMEM, sB>>>(scoreA, permA, nmapA, 8192);
    cudaStreamWaitEvent(sB, eScat, 0);
    k_degscore1<<<256, 256, 0, sB>>>();
    cudaEventRecord(eDS1, sB);
    k_rank<8><<<G, 1024, RSMEM, sB>>>(scoreB, permB, nmapB, 4096);
    k_degscore2<<<128, 256, 0, sB>>>();
    cudaEventRecord(eDS2, sB);

    // main: remaining aggregation chain
    cudaStreamWaitEvent(0, eDS1, 0);
    k_agg<1><<<8192, 256>>>(h0, pack1, al1,
                            al2, pack2, att_l + 2*CC, att_r + 2*CC, h1, 13, 1);
    cudaStreamWaitEvent(0, eDS2, 0);
    k_agg<2><<<4096, 256>>>(h1, pack2, al2,
                            nullptr, nullptr, nullptr, nullptr, nullptr, 12, 2);
    cudaEventRecord(eA2, 0);

    // cleanup for next replay on sB (parallel with head), then join
    cudaStreamWaitEvent(sB, eA2, 0);
    k_cleanup<<<512, 256, 0, sB>>>();
    cudaEventRecord(eCl, sB);

    k_head<<<G, 256>>>(w_ih, b_ih, b_hh, w_fin, b_fin, w_root, b_root,
                       root, alpha, out);
    cudaStreamWaitEvent(0, eCl, 0);
}